// round 10
// baseline (speedup 1.0000x reference)
#include <cuda_runtime.h>

// out[row] = alpha(||p_row||, ||p_row * w||) * (p_row * w)
// alpha folds expmap0 -> mobius diag scaling -> project -> logmap0 into one
// scalar per row. Single pass: row stays in registers, streaming cache hints.
// R9 champion structure; 128-thread CTAs to reduce per-CTA L1tex burst depth
// and multi-CTA spread.

#define NCOLS 512
#define WARPS_PER_BLOCK 4

__global__ __launch_bounds__(WARPS_PER_BLOCK * 32)
void hyp_adapter_kernel(const float* __restrict__ params,
                        const float* __restrict__ weights,
                        float* __restrict__ out,
                        int nrows)
{
    const int warp_global = (blockIdx.x * (WARPS_PER_BLOCK * 32) + threadIdx.x) >> 5;
    const int lane = threadIdx.x & 31;
    if (warp_global >= nrows) return;

    const float4* __restrict__ prow = reinterpret_cast<const float4*>(params) +
                                      (size_t)warp_global * (NCOLS / 4);
    const float4* __restrict__ w4 = reinterpret_cast<const float4*>(weights);

    float4 v[4];
    float4 wv[4];

    // Front-batch all loads: params streaming (evict-first), weights retained.
#pragma unroll
    for (int j = 0; j < 4; ++j) {
        v[j]  = __ldcs(&prow[j * 32 + lane]);
        wv[j] = __ldg(&w4[j * 32 + lane]);
    }

    float s1 = 0.0f;  // sum p^2
    float s2 = 0.0f;  // sum (p*w)^2
#pragma unroll
    for (int j = 0; j < 4; ++j) {
        float4 a = v[j], b = wv[j];
        s1 = fmaf(a.x, a.x, s1);
        s1 = fmaf(a.y, a.y, s1);
        s1 = fmaf(a.z, a.z, s1);
        s1 = fmaf(a.w, a.w, s1);
        float mx0 = a.x * b.x, mx1 = a.y * b.y, mx2 = a.z * b.z, mx3 = a.w * b.w;
        s2 = fmaf(mx0, mx0, s2);
        s2 = fmaf(mx1, mx1, s2);
        s2 = fmaf(mx2, mx2, s2);
        s2 = fmaf(mx3, mx3, s2);
    }

#pragma unroll
    for (int off = 16; off > 0; off >>= 1) {
        s1 += __shfl_xor_sync(0xFFFFFFFFu, s1, off);
        s2 += __shfl_xor_sync(0xFFFFFFFFu, s2, off);
    }

    const float SQRT_C = 0.1f;
    const float EPS    = 1e-5f;
    const float MIN_N  = 1e-5f;

    float n1 = sqrtf(s1);                 // ||p||
    float n2 = sqrtf(s2);                 // ||p*w||

    // expmap0: x = s * p
    float u_norm = fmaxf(n1, MIN_N);
    float su = SQRT_C * u_norm;
    float s = tanhf(su) / su;

    // mobius diag scaling
    float x_norm  = fmaxf(s * n1, MIN_N);
    float mx_norm = s * n2;               // NOT clamped (matches torch)
    float cx = fminf(fmaxf(SQRT_C * x_norm, -1.0f + EPS), 1.0f - EPS);
    float at = atanhf(cx);
    float tn = tanhf((mx_norm / x_norm) * at);
    float beta = tn * s / (mx_norm * SQRT_C);   // res = beta * (p*w)
    float res_norm = tn / SQRT_C;               // ||res||

    // project
    float rn = fmaxf(res_norm, MIN_N);
    float maxnorm = (1.0f - 0.001f) / SQRT_C;
    float gamma = (rn > maxnorm) ? (maxnorm / rn) : 1.0f;

    // logmap0
    float y_norm = fmaxf(gamma * res_norm, MIN_N);
    float cy = fminf(fmaxf(SQRT_C * y_norm, -1.0f + EPS), 1.0f - EPS);
    float at2 = atanhf(cy);
    float alpha = gamma * beta * at2 / (y_norm * SQRT_C);

    float4* __restrict__ orow = reinterpret_cast<float4*>(out) +
                                (size_t)warp_global * (NCOLS / 4);
#pragma unroll
    for (int j = 0; j < 4; ++j) {
        float4 a = v[j], b = wv[j];
        float4 o;
        o.x = alpha * (a.x * b.x);
        o.y = alpha * (a.y * b.y);
        o.z = alpha * (a.z * b.z);
        o.w = alpha * (a.w * b.w);
        __stcs(&orow[j * 32 + lane], o);
    }
}

extern "C" void kernel_launch(void* const* d_in, const int* in_sizes, int n_in,
                              void* d_out, int out_size)
{
    const float* params  = (const float*)d_in[0];
    const float* weights = (const float*)d_in[1];
    float* out = (float*)d_out;

    int nrows = in_sizes[0] / NCOLS;   // 131072
    int blocks = (nrows + WARPS_PER_BLOCK - 1) / WARPS_PER_BLOCK;

    hyp_adapter_kernel<<<blocks, WARPS_PER_BLOCK * 32>>>(params, weights, out, nrows);
}

// round 11
// speedup vs baseline: 1.0086x; 1.0086x over previous
#include <cuda_runtime.h>

// out[row] = alpha(||p_row||, ||p_row * w||) * (p_row * w)
// alpha folds expmap0 -> mobius diag scaling -> project -> logmap0 into one
// scalar per row. Single fused pass: row stays in registers, streaming cache
// hints. CONVERGED champion: 81.7 us, DRAM ~79.5% = measured GB300 ceiling
// for a balanced fp32 read+write stream; 512 MB traffic is irreducible.

#define NCOLS 512
#define WARPS_PER_BLOCK 8

__global__ __launch_bounds__(WARPS_PER_BLOCK * 32)
void hyp_adapter_kernel(const float* __restrict__ params,
                        const float* __restrict__ weights,
                        float* __restrict__ out,
                        int nrows)
{
    const int warp_global = (blockIdx.x * (WARPS_PER_BLOCK * 32) + threadIdx.x) >> 5;
    const int lane = threadIdx.x & 31;
    if (warp_global >= nrows) return;

    const float4* __restrict__ prow = reinterpret_cast<const float4*>(params) +
                                      (size_t)warp_global * (NCOLS / 4);
    const float4* __restrict__ w4 = reinterpret_cast<const float4*>(weights);

    float4 v[4];
    float4 wv[4];

    // Front-batch all loads: params streaming (evict-first), weights retained.
#pragma unroll
    for (int j = 0; j < 4; ++j) {
        v[j]  = __ldcs(&prow[j * 32 + lane]);
        wv[j] = __ldg(&w4[j * 32 + lane]);
    }

    float s1 = 0.0f;  // sum p^2
    float s2 = 0.0f;  // sum (p*w)^2
#pragma unroll
    for (int j = 0; j < 4; ++j) {
        float4 a = v[j], b = wv[j];
        s1 = fmaf(a.x, a.x, s1);
        s1 = fmaf(a.y, a.y, s1);
        s1 = fmaf(a.z, a.z, s1);
        s1 = fmaf(a.w, a.w, s1);
        float mx0 = a.x * b.x, mx1 = a.y * b.y, mx2 = a.z * b.z, mx3 = a.w * b.w;
        s2 = fmaf(mx0, mx0, s2);
        s2 = fmaf(mx1, mx1, s2);
        s2 = fmaf(mx2, mx2, s2);
        s2 = fmaf(mx3, mx3, s2);
    }

#pragma unroll
    for (int off = 16; off > 0; off >>= 1) {
        s1 += __shfl_xor_sync(0xFFFFFFFFu, s1, off);
        s2 += __shfl_xor_sync(0xFFFFFFFFu, s2, off);
    }

    const float SQRT_C = 0.1f;
    const float EPS    = 1e-5f;
    const float MIN_N  = 1e-5f;

    float n1 = sqrtf(s1);                 // ||p||
    float n2 = sqrtf(s2);                 // ||p*w||

    // expmap0: x = s * p
    float u_norm = fmaxf(n1, MIN_N);
    float su = SQRT_C * u_norm;
    float s = tanhf(su) / su;

    // mobius diag scaling
    float x_norm  = fmaxf(s * n1, MIN_N);
    float mx_norm = s * n2;               // NOT clamped (matches torch)
    float cx = fminf(fmaxf(SQRT_C * x_norm, -1.0f + EPS), 1.0f - EPS);
    float at = atanhf(cx);
    float tn = tanhf((mx_norm / x_norm) * at);
    float beta = tn * s / (mx_norm * SQRT_C);   // res = beta * (p*w)
    float res_norm = tn / SQRT_C;               // ||res||

    // project
    float rn = fmaxf(res_norm, MIN_N);
    float maxnorm = (1.0f - 0.001f) / SQRT_C;
    float gamma = (rn > maxnorm) ? (maxnorm / rn) : 1.0f;

    // logmap0
    float y_norm = fmaxf(gamma * res_norm, MIN_N);
    float cy = fminf(fmaxf(SQRT_C * y_norm, -1.0f + EPS), 1.0f - EPS);
    float at2 = atanhf(cy);
    float alpha = gamma * beta * at2 / (y_norm * SQRT_C);

    float4* __restrict__ orow = reinterpret_cast<float4*>(out) +
                                (size_t)warp_global * (NCOLS / 4);
#pragma unroll
    for (int j = 0; j < 4; ++j) {
        float4 a = v[j], b = wv[j];
        float4 o;
        o.x = alpha * (a.x * b.x);
        o.y = alpha * (a.y * b.y);
        o.z = alpha * (a.z * b.z);
        o.w = alpha * (a.w * b.w);
        __stcs(&orow[j * 32 + lane], o);
    }
}

extern "C" void kernel_launch(void* const* d_in, const int* in_sizes, int n_in,
                              void* d_out, int out_size)
{
    const float* params  = (const float*)d_in[0];
    const float* weights = (const float*)d_in[1];
    float* out = (float*)d_out;

    int nrows = in_sizes[0] / NCOLS;   // 131072
    int blocks = (nrows + WARPS_PER_BLOCK - 1) / WARPS_PER_BLOCK;

    hyp_adapter_kernel<<<blocks, WARPS_PER_BLOCK * 32>>>(params, weights, out, nrows);
}